// round 3
// baseline (speedup 1.0000x reference)
#include <cuda_runtime.h>
#include <cstdint>

#define NBATCH 8
#define CHN 8
#define HH 512
#define HB 256
#define RSQ2 0.70710678118654752440f
#define SQ2F 1.41421356237309504880f
#define SECSZ (NBATCH*CHN*HB*HB)   /* 4194304 */

// ---------------- scratch (static __device__, allowed) ----------------
__device__ float g_Sx [NBATCH*HH*HH];   // channel sum of X
__device__ float g_T1 [NBATCH*HH*HH];   // row-conv temp
__device__ float g_B  [NBATCH*HH*HH];   // per-channel lowpass reconstruction term
__device__ float g_Sd [NBATCH*HH*HH];   // Sx - 8*B
__device__ float g_cp [NBATCH*HB*HB];   // pooled lowpass
__device__ float g_Sp0[NBATCH*HB*HH];
__device__ float g_Sp1[NBATCH*HB*HH];
__device__ float g_Ct [NBATCH*HB*HH];   // col-conv temp (level1, reused)
__device__ float g_F1 [NBATCH*HB*HH];
__device__ float g_Sx0[NBATCH*HB*HH];
__device__ float g_F2 [NBATCH*HB*HH];
__device__ float g_Sxx[NBATCH*HB*HH];
__device__ float g_SP0[NBATCH*HB*HB];
__device__ float g_SP1[NBATCH*HB*HB];
__device__ float g_Dt [NBATCH*HB*HB];   // col-conv temp (level2, reused)
__device__ float g_G1 [NBATCH*HB*HB];
__device__ float g_Se0[NBATCH*HB*HB];
__device__ float g_G2 [NBATCH*HB*HB];

// ---------------- kernels ----------------

// 1) Sx[n,i,j] = sum_c X[n,c,i,j]   (float4 vectorized)
__global__ void ksum(const float* __restrict__ X) {
    int idx = blockIdx.x * blockDim.x + threadIdx.x;      // < NBATCH*HH*HH/4
    int n = idx >> 16;                                    // HH*HH/4 = 65536
    const float4* xb = reinterpret_cast<const float4*>(X)
                       + (size_t)n * CHN * 65536 + (idx & 65535);
    float4 a = xb[0];
#pragma unroll
    for (int c = 1; c < CHN; c++) {
        float4 v = xb[(size_t)c * 65536];
        a.x += v.x; a.y += v.y; a.z += v.z; a.w += v.w;
    }
    reinterpret_cast<float4*>(g_Sx)[idx] = a;
}

// 2) row pass of conv_per(Sx, h) along j (9 taps, periodic 512)
__global__ void krowH(const float* __restrict__ h) {
    int idx = blockIdx.x * blockDim.x + threadIdx.x;      // < NBATCH*HH*HH
    int j = idx & 511;
    const float* row = g_Sx + (idx - j);
    float acc = 0.f;
#pragma unroll
    for (int a = 0; a < 9; a++) acc += h[a] * row[(j + a - 4) & 511];
    g_T1[idx] = acc;
}

// 3) col pass of conv h + 2x2 avgpool -> cp ; also write output section 0
__global__ void kpool(const float* __restrict__ h, float* __restrict__ out) {
    int idx = blockIdx.x * blockDim.x + threadIdx.x;      // < NBATCH*HB*HB
    int n = idx >> 16;
    int rem = idx & 65535;
    int p = rem >> 8, q = rem & 255;
    const float* T = g_T1 + ((size_t)n << 18);
    float acc = 0.f;
#pragma unroll
    for (int a = 0; a < 9; a++) {
        int r0 = ((2 * p + a - 4) & 511) << 9;
        int r1 = ((2 * p + 1 + a - 4) & 511) << 9;
        float2 t0 = *reinterpret_cast<const float2*>(T + r0 + 2 * q);
        float2 t1 = *reinterpret_cast<const float2*>(T + r1 + 2 * q);
        acc += h[a] * (t0.x + t0.y + t1.x + t1.y);
    }
    acc *= 0.25f;
    g_cp[idx] = acc;
    size_t base = (size_t)(n * CHN) * 65536 + rem;
#pragma unroll
    for (int c = 0; c < CHN; c++) out[base + (size_t)c * 65536] = acc;
}

// 4) B = 8*conv_per(up2(cp), g x g) (polyphase); Sd = Sx - 8*B
__global__ void kBSd(const float* __restrict__ g) {
    int idx = blockIdx.x * blockDim.x + threadIdx.x;      // < NBATCH*HH*HH
    int n = idx >> 18;
    int i = (idx >> 9) & 511, j = idx & 511;
    const float* cpb = g_cp + ((size_t)n << 16);
    float gv[7];
#pragma unroll
    for (int a = 0; a < 7; a++) gv[a] = g[a];
    float acc = 0.f;
#pragma unroll
    for (int a = 0; a < 7; a++) {
        if (((i + a) & 1) == 1) {                         // up-row even
            int tr = (((i + a - 3) & 511) >> 1) << 8;
            float inner = 0.f;
#pragma unroll
            for (int b = 0; b < 7; b++) {
                if (((j + b) & 1) == 1) {
                    int u = ((j + b - 3) & 511) >> 1;
                    inner += gv[b] * cpb[tr + u];
                }
            }
            acc += gv[a] * inner;
        }
    }
    float Bs = 8.f * acc;
    g_B[idx] = Bs;
    g_Sd[idx] = g_Sx[idx] - 8.f * Bs;
}

// 5) Sp0[r,s] = Sd[(r-s)%512, (r+s)%512] ; Sp1 same row, col+1
__global__ void kremap1() {
    int idx = blockIdx.x * blockDim.x + threadIdx.x;      // < NBATCH*HB*HH
    int n = idx >> 17;
    int rem = idx & 131071;
    int r = rem >> 9, s = rem & 511;
    const float* Sd = g_Sd + ((size_t)n << 18);
    int t = ((r - s) & 511) << 9;
    int v = (r + s) & 511;
    g_Sp0[idx] = Sd[t + v];
    g_Sp1[idx] = Sd[t + ((v + 1) & 511)];
}

// generic 12-tap periodic column convs
#define DEF_COLF(name, INV, OUTV, W, CL)                                     \
__global__ void name(const float* __restrict__ f) {                          \
    int idx = blockIdx.x * blockDim.x + threadIdx.x;                         \
    int j = idx & (W - 1);                                                   \
    const float* row = INV + (idx - j);                                      \
    float acc = 0.f;                                                         \
    for (int b = 0; b < 12; b++) acc += f[b] * row[(j + b - CL) & (W - 1)];  \
    OUTV[idx] = acc;                                                         \
}
DEF_COLF(kcolq1, g_Sp1, g_Ct, 512, 6)
DEF_COLF(kcolq2, g_Sx0, g_Ct, 512, 5)
DEF_COLF(kcolp1, g_SP1, g_Dt, 256, 6)
DEF_COLF(kcolp2, g_Se0, g_Dt, 256, 5)

// 7) qper_col row pass (level1, shift(1,1): ru=6) -> F1 ; Sx0 = (Sp0 - 8F1)/sqrt2
__global__ void krowq1(const float* __restrict__ f) {
    int idx = blockIdx.x * blockDim.x + threadIdx.x;      // < NBATCH*HB*HH
    int rem = idx & 131071;
    int r = rem >> 9, s = idx & 511;
    const float* C = g_Ct + (idx - rem);
    float acc = 0.f;
#pragma unroll
    for (int a = 0; a < 12; a++) {
        int t = r + a - 6;
        float v = ((unsigned)t < 256u) ? C[(t << 9) + s]
                                       : C[((t & 255) << 9) + ((s + 256) & 511)];
        acc += f[a] * v;
    }
    g_F1[idx] = acc;
    g_Sx0[idx] = (g_Sp0[idx] - 8.f * acc) * RSQ2;
}

// 9) qper_col row pass (shift(0,0): ru=5) -> F2 ; Sxx = Sx0 - sqrt2*Sp1 - 8*F2
__global__ void krowq2(const float* __restrict__ f) {
    int idx = blockIdx.x * blockDim.x + threadIdx.x;
    int rem = idx & 131071;
    int r = rem >> 9, s = idx & 511;
    const float* C = g_Ct + (idx - rem);
    float acc = 0.f;
#pragma unroll
    for (int a = 0; a < 12; a++) {
        int t = r + a - 5;
        float v = ((unsigned)t < 256u) ? C[(t << 9) + s]
                                       : C[((t & 255) << 9) + ((s + 256) & 511)];
        acc += f[a] * v;
    }
    g_F2[idx] = acc;
    g_Sxx[idx] = g_Sx0[idx] - SQ2F * g_Sp1[idx] - 8.f * acc;
}

// 10) level-2 quincunx remap.
//     I=(i+j)%256, u=(2j-I)%512           -> SP0[i,j] = Sxx[I, u]
//     I1=(I+1)%256, s1=(2j+1-I1)%512      -> SP1[i,j] = Sxx[I1, s1]
//     (s1==u except on the wrap row I==255, where s1 = 2j+1 = u+256 mod 512)
__global__ void kremap2() {
    int idx = blockIdx.x * blockDim.x + threadIdx.x;      // < NBATCH*HB*HB
    int n = idx >> 16;
    int rem = idx & 65535;
    int i = rem >> 8, j = rem & 255;
    const float* Sxx = g_Sxx + ((size_t)n << 17);
    int ipj = i + j;
    int u = (j - i + ((ipj >= 256) ? 256 : 0)) & 511;
    int I1 = (ipj + 1) & 255;
    int s1 = (ipj == 255) ? (2 * j + 1) : u;
    g_SP0[idx] = Sxx[((ipj & 255) << 9) + u];
    g_SP1[idx] = Sxx[(I1 << 9) + s1];
}

// 12) per row pass (ru=6) -> G1 ; Se0 = (SP0 - 16 G1)/sqrt2
__global__ void krowp1(const float* __restrict__ f) {
    int idx = blockIdx.x * blockDim.x + threadIdx.x;      // < NBATCH*HB*HB
    int rem = idx & 65535;
    int i = rem >> 8, j = idx & 255;
    const float* D = g_Dt + (idx - rem);
    float acc = 0.f;
#pragma unroll
    for (int a = 0; a < 12; a++)
        acc += f[a] * D[(((i + a - 6) & 255) << 8) + j];
    g_G1[idx] = acc;
    g_Se0[idx] = (g_SP0[idx] - 16.f * acc) * RSQ2;
}

// 14) per row pass (ru=5) -> G2
__global__ void krowp2(const float* __restrict__ f) {
    int idx = blockIdx.x * blockDim.x + threadIdx.x;
    int rem = idx & 65535;
    int i = rem >> 8, j = idx & 255;
    const float* D = g_Dt + (idx - rem);
    float acc = 0.f;
#pragma unroll
    for (int a = 0; a < 12; a++)
        acc += f[a] * D[(((i + a - 5) & 255) << 8) + j];
    g_G2[idx] = acc;
}

// 15) final combine.  With I=(i+j)%256, u=(2j-I)%512, I1=(i+j+1)%256,
//     s1=(2j+1-I1)%512:
//       e0[:, :8][i,j] = 0.5*X[2i,2j]     - (0.5*(B[2i,2j]+F1[I,u]) + RSQ2*G1)
//       e0[:, 8:][i,j] = -X[2i,2j+1]      + (B[2i,2j+1] - RSQ2*(F2[I,u]+G1))
//       e1[:, :8][i,j] = -X[2i+1,2j+1]    + (B[2i+1,2j+1] + F1[I1,s1] - G2)
//       e1[:, 8:][i,j] = 2*X[2i+1,(2j+2)%512] + (-2*B[2i+1,(2j+2)%512] + SQ2F*F2[I1,s1] - G2)
__global__ void kfinal(const float* __restrict__ X, float* __restrict__ out) {
    int idx = blockIdx.x * blockDim.x + threadIdx.x;      // < NBATCH*HB*HB
    int n = idx >> 16;
    int rem = idx & 65535;
    int i = rem >> 8, j = rem & 255;

    const float* B  = g_B  + ((size_t)n << 18);
    const float* F1 = g_F1 + ((size_t)n << 17);
    const float* F2 = g_F2 + ((size_t)n << 17);
    float g1 = g_G1[idx], g2 = g_G2[idx];

    int ipj = i + j;
    int d0 = (ipj >= 256) ? 256 : 0;
    int u  = (j - i + d0) & 511;
    int r  = ipj & 255;
    int r1 = (ipj + 1) & 255;
    int s1 = (ipj == 255) ? (2 * j + 1) : u;

    int rowE = 2 * i, colE = 2 * j, colEp = 2 * j + 1;
    int rowO = 2 * i + 1;
    int colO = 2 * j + 1;
    int colO2 = (2 * j + 2) & 511;

    float b00 = B[(rowE << 9) + colE ];
    float b01 = B[(rowE << 9) + colEp];
    float b10 = B[(rowO << 9) + colO ];
    float b11 = B[(rowO << 9) + colO2];
    float f1a = F1[(r  << 9) + u];
    float f1b = F1[(r1 << 9) + s1];
    float f2a = F2[(r  << 9) + u];
    float f2b = F2[(r1 << 9) + s1];

    float K0 = 0.5f * (b00 + f1a) + g1 * RSQ2;            // e0a = 0.5*X - K0
    float K1 = b01 - (f2a + g1) * RSQ2;                   // e0b = -X + K1
    float K2 = b10 + f1b - g2;                            // e1a = -X + K2
    float K3 = -2.f * b11 + SQ2F * f2b - g2;              // e1b = 2*X + K3

    const float* Xn = X + ((size_t)(n * CHN) << 18);
    size_t obase = (size_t)(n * CHN) * 65536 + rem;
    int xiE = rowE << 9, xiO = rowO << 9;
#pragma unroll
    for (int c = 0; c < CHN; c++) {
        const float* Xc = Xn + ((size_t)c << 18);
        size_t o = obase + (size_t)c * 65536;
        out[(size_t)SECSZ * 1 + o] = -Xc[xiO + colO ] + K2;        // e1[:, :8]
        out[(size_t)SECSZ * 2 + o] = 0.5f * Xc[xiE + colE] - K0;   // e0[:, :8]
        out[(size_t)SECSZ * 3 + o] = 2.f * Xc[xiO + colO2] + K3;   // e1[:, 8:]
        out[(size_t)SECSZ * 4 + o] = -Xc[xiE + colEp] + K1;        // e0[:, 8:]
    }
}

// ---------------- launch ----------------
extern "C" void kernel_launch(void* const* d_in, const int* in_sizes, int n_in,
                              void* d_out, int out_size) {
    const float* X = (const float*)d_in[0];
    const float* h = (const float*)d_in[1];
    const float* g = (const float*)d_in[2];
    const float* f = (const float*)d_in[3];
    float* out = (float*)d_out;

    ksum   <<<2048, 256>>>(X);
    krowH  <<<8192, 256>>>(h);
    kpool  <<<2048, 256>>>(h, out);
    kBSd   <<<8192, 256>>>(g);
    kremap1<<<4096, 256>>>();
    kcolq1 <<<4096, 256>>>(f);
    krowq1 <<<4096, 256>>>(f);
    kcolq2 <<<4096, 256>>>(f);
    krowq2 <<<4096, 256>>>(f);
    kremap2<<<2048, 256>>>();
    kcolp1 <<<2048, 256>>>(f);
    krowp1 <<<2048, 256>>>(f);
    kcolp2 <<<2048, 256>>>(f);
    krowp2 <<<2048, 256>>>(f);
    kfinal <<<2048, 256>>>(X, out);
}

// round 4
// speedup vs baseline: 1.1157x; 1.1157x over previous
#include <cuda_runtime.h>
#include <cstdint>

#define NBATCH 8
#define CHN 8
#define HH 512
#define HB 256
#define RSQ2 0.70710678118654752440f
#define SQ2F 1.41421356237309504880f
#define SECSZ (NBATCH*CHN*HB*HB)   /* 4194304 */

// ---------------- scratch ----------------
__device__ float g_Sx [NBATCH*HH*HH];
__device__ float g_T1 [NBATCH*HH*HH];
__device__ float g_B  [NBATCH*HH*HH];
__device__ float g_Sd [NBATCH*HH*HH];
__device__ float g_cp [NBATCH*HB*HB];
__device__ float g_Sp0[NBATCH*HB*HH];
__device__ float g_Sp1[NBATCH*HB*HH];
__device__ float g_Ct [NBATCH*HB*HH];
__device__ float g_F1 [NBATCH*HB*HH];
__device__ float g_Sx0[NBATCH*HB*HH];
__device__ float g_F2 [NBATCH*HB*HH];
__device__ float g_Sxx[NBATCH*HB*HH];
__device__ float g_SP0[NBATCH*HB*HB];
__device__ float g_SP1[NBATCH*HB*HB];
__device__ float g_Dt [NBATCH*HB*HB];
__device__ float g_G1 [NBATCH*HB*HB];
__device__ float g_Se0[NBATCH*HB*HB];
__device__ float g_G2 [NBATCH*HB*HB];

// ---------------- kernels ----------------

// 1) fused: Sx = channel-sum of X  AND  T1 = row conv(h, per) of Sx.
//    One block per (n,row). 128 threads, float4 per thread.
__global__ void ksumrow(const float* __restrict__ X, const float* __restrict__ h) {
    __shared__ float srow[HH];
    int row = blockIdx.x;                       // 0..NBATCH*HH-1
    int n = row >> 9;
    int t = threadIdx.x;                        // 0..127
    const float4* xb = reinterpret_cast<const float4*>(X)
                       + (size_t)n * CHN * 65536 + (size_t)(row & 511) * 128 + t;
    float4 a = xb[0];
#pragma unroll
    for (int c = 1; c < CHN; c++) {
        float4 v = xb[(size_t)c * 65536];
        a.x += v.x; a.y += v.y; a.z += v.z; a.w += v.w;
    }
    reinterpret_cast<float4*>(srow)[t] = a;
    reinterpret_cast<float4*>(g_Sx)[(size_t)row * 128 + t] = a;
    __syncthreads();
    float hv[9];
#pragma unroll
    for (int k = 0; k < 9; k++) hv[k] = h[k];
    float4 o;
    float* op = &o.x;
#pragma unroll
    for (int k = 0; k < 4; k++) {
        int j = 4 * t + k;
        float acc = 0.f;
#pragma unroll
        for (int a2 = 0; a2 < 9; a2++) acc += hv[a2] * srow[(j + a2 - 4) & 511];
        op[k] = acc;
    }
    reinterpret_cast<float4*>(g_T1)[(size_t)row * 128 + t] = o;
}

// 3) col pass of conv h + 2x2 avgpool -> cp ; also write output section 0
__global__ void kpool(const float* __restrict__ h, float* __restrict__ out) {
    int idx = blockIdx.x * blockDim.x + threadIdx.x;      // < NBATCH*HB*HB
    int n = idx >> 16;
    int rem = idx & 65535;
    int p = rem >> 8, q = rem & 255;
    const float* T = g_T1 + ((size_t)n << 18);
    float acc = 0.f;
#pragma unroll
    for (int a = 0; a < 9; a++) {
        int r0 = ((2 * p + a - 4) & 511) << 9;
        int r1 = ((2 * p + 1 + a - 4) & 511) << 9;
        float2 t0 = *reinterpret_cast<const float2*>(T + r0 + 2 * q);
        float2 t1 = *reinterpret_cast<const float2*>(T + r1 + 2 * q);
        acc += h[a] * (t0.x + t0.y + t1.x + t1.y);
    }
    acc *= 0.25f;
    g_cp[idx] = acc;
    size_t base = (size_t)(n * CHN) * 65536 + rem;
#pragma unroll
    for (int c = 0; c < CHN; c++) out[base + (size_t)c * 65536] = acc;
}

// 4) B = 8*conv_per(up2(cp), g x g) polyphase, parity-specialized; Sd = Sx - 8*B
__global__ void kBSd(const float* __restrict__ g) {
    int idx = blockIdx.x * blockDim.x + threadIdx.x;      // < NBATCH*HH*HH
    int n = idx >> 18;
    int i = (idx >> 9) & 511, j = idx & 511;
    const float* cpb = g_cp + ((size_t)n << 16);
    float gv[7];
#pragma unroll
    for (int a = 0; a < 7; a++) gv[a] = g[a];

    // rows: taps a with (i+a) odd; cols: taps b with (j+b) odd
    float gr[4], gc[4];
    int ir[4], jc[4];
    if (i & 1) {
        gr[0] = gv[0]; gr[1] = gv[2]; gr[2] = gv[4]; gr[3] = gv[6];
        ir[0] = ((i - 3) & 511) >> 1; ir[1] = ((i - 1) & 511) >> 1;
        ir[2] = ((i + 1) & 511) >> 1; ir[3] = ((i + 3) & 511) >> 1;
    } else {
        gr[0] = gv[1]; gr[1] = gv[3]; gr[2] = gv[5]; gr[3] = 0.f;
        ir[0] = ((i - 2) & 511) >> 1; ir[1] = i >> 1;
        ir[2] = ((i + 2) & 511) >> 1; ir[3] = ir[0];
    }
    if (j & 1) {
        gc[0] = gv[0]; gc[1] = gv[2]; gc[2] = gv[4]; gc[3] = gv[6];
        jc[0] = ((j - 3) & 511) >> 1; jc[1] = ((j - 1) & 511) >> 1;
        jc[2] = ((j + 1) & 511) >> 1; jc[3] = ((j + 3) & 511) >> 1;
    } else {
        gc[0] = gv[1]; gc[1] = gv[3]; gc[2] = gv[5]; gc[3] = 0.f;
        jc[0] = ((j - 2) & 511) >> 1; jc[1] = j >> 1;
        jc[2] = ((j + 2) & 511) >> 1; jc[3] = jc[0];
    }
    float acc = 0.f;
#pragma unroll
    for (int a = 0; a < 4; a++) {
        const float* rowp = cpb + (ir[a] << 8);
        float inner = gc[0] * rowp[jc[0]] + gc[1] * rowp[jc[1]]
                    + gc[2] * rowp[jc[2]] + gc[3] * rowp[jc[3]];
        acc += gr[a] * inner;
    }
    float Bs = 8.f * acc;
    g_B[idx] = Bs;
    g_Sd[idx] = g_Sx[idx] - 8.f * Bs;
}

// 5) Sp0[r,s] = Sd[(r-s)%512, (r+s)%512] ; Sp1 same row, col+1
__global__ void kremap1() {
    int idx = blockIdx.x * blockDim.x + threadIdx.x;      // < NBATCH*HB*HH
    int n = idx >> 17;
    int rem = idx & 131071;
    int r = rem >> 9, s = rem & 511;
    const float* Sd = g_Sd + ((size_t)n << 18);
    int t = ((r - s) & 511) << 9;
    int v = (r + s) & 511;
    g_Sp0[idx] = Sd[t + v];
    g_Sp1[idx] = Sd[t + ((v + 1) & 511)];
}

// generic 12-tap periodic column convs
#define DEF_COLF(name, INV, OUTV, W, CL)                                     \
__global__ void name(const float* __restrict__ f) {                          \
    int idx = blockIdx.x * blockDim.x + threadIdx.x;                         \
    int j = idx & (W - 1);                                                   \
    const float* row = INV + (idx - j);                                      \
    float acc = 0.f;                                                         \
    for (int b = 0; b < 12; b++) acc += f[b] * row[(j + b - CL) & (W - 1)];  \
    OUTV[idx] = acc;                                                         \
}
DEF_COLF(kcolq1, g_Sp1, g_Ct, 512, 6)
DEF_COLF(kcolq2, g_Sx0, g_Ct, 512, 5)
DEF_COLF(kcolp1, g_SP1, g_Dt, 256, 6)
DEF_COLF(kcolp2, g_Se0, g_Dt, 256, 5)

// 7) qper_col row pass (ru=6) -> F1 ; Sx0 = (Sp0 - 8F1)/sqrt2
__global__ void krowq1(const float* __restrict__ f) {
    int idx = blockIdx.x * blockDim.x + threadIdx.x;      // < NBATCH*HB*HH
    int rem = idx & 131071;
    int r = rem >> 9, s = idx & 511;
    const float* C = g_Ct + (idx - rem);
    float acc = 0.f;
#pragma unroll
    for (int a = 0; a < 12; a++) {
        int t = r + a - 6;
        float v = ((unsigned)t < 256u) ? C[(t << 9) + s]
                                       : C[((t & 255) << 9) + ((s + 256) & 511)];
        acc += f[a] * v;
    }
    g_F1[idx] = acc;
    g_Sx0[idx] = (g_Sp0[idx] - 8.f * acc) * RSQ2;
}

// 9) qper_col row pass (ru=5) -> F2 ; Sxx = Sx0 - sqrt2*Sp1 - 8*F2
__global__ void krowq2(const float* __restrict__ f) {
    int idx = blockIdx.x * blockDim.x + threadIdx.x;
    int rem = idx & 131071;
    int r = rem >> 9, s = idx & 511;
    const float* C = g_Ct + (idx - rem);
    float acc = 0.f;
#pragma unroll
    for (int a = 0; a < 12; a++) {
        int t = r + a - 5;
        float v = ((unsigned)t < 256u) ? C[(t << 9) + s]
                                       : C[((t & 255) << 9) + ((s + 256) & 511)];
        acc += f[a] * v;
    }
    g_F2[idx] = acc;
    g_Sxx[idx] = g_Sx0[idx] - SQ2F * g_Sp1[idx] - 8.f * acc;
}

// 10) level-2 quincunx remap.
__global__ void kremap2() {
    int idx = blockIdx.x * blockDim.x + threadIdx.x;      // < NBATCH*HB*HB
    int n = idx >> 16;
    int rem = idx & 65535;
    int i = rem >> 8, j = rem & 255;
    const float* Sxx = g_Sxx + ((size_t)n << 17);
    int ipj = i + j;
    int u = (j - i + ((ipj >= 256) ? 256 : 0)) & 511;
    int I1 = (ipj + 1) & 255;
    int s1 = (ipj == 255) ? (2 * j + 1) : u;
    g_SP0[idx] = Sxx[((ipj & 255) << 9) + u];
    g_SP1[idx] = Sxx[(I1 << 9) + s1];
}

// 12) per row pass (ru=6) -> G1 ; Se0 = (SP0 - 16 G1)/sqrt2
__global__ void krowp1(const float* __restrict__ f) {
    int idx = blockIdx.x * blockDim.x + threadIdx.x;      // < NBATCH*HB*HB
    int rem = idx & 65535;
    int i = rem >> 8, j = idx & 255;
    const float* D = g_Dt + (idx - rem);
    float acc = 0.f;
#pragma unroll
    for (int a = 0; a < 12; a++)
        acc += f[a] * D[(((i + a - 6) & 255) << 8) + j];
    g_G1[idx] = acc;
    g_Se0[idx] = (g_SP0[idx] - 16.f * acc) * RSQ2;
}

// 14) per row pass (ru=5) -> G2
__global__ void krowp2(const float* __restrict__ f) {
    int idx = blockIdx.x * blockDim.x + threadIdx.x;
    int rem = idx & 65535;
    int i = rem >> 8, j = idx & 255;
    const float* D = g_Dt + (idx - rem);
    float acc = 0.f;
#pragma unroll
    for (int a = 0; a < 12; a++)
        acc += f[a] * D[(((i + a - 5) & 255) << 8) + j];
    g_G2[idx] = acc;
}

// 15) final combine.
__global__ void kfinal(const float* __restrict__ X, float* __restrict__ out) {
    int idx = blockIdx.x * blockDim.x + threadIdx.x;      // < NBATCH*HB*HB
    int n = idx >> 16;
    int rem = idx & 65535;
    int i = rem >> 8, j = rem & 255;

    const float* B  = g_B  + ((size_t)n << 18);
    const float* F1 = g_F1 + ((size_t)n << 17);
    const float* F2 = g_F2 + ((size_t)n << 17);
    float g1 = g_G1[idx], g2 = g_G2[idx];

    int ipj = i + j;
    int d0 = (ipj >= 256) ? 256 : 0;
    int u  = (j - i + d0) & 511;
    int r  = ipj & 255;
    int r1 = (ipj + 1) & 255;
    int s1 = (ipj == 255) ? (2 * j + 1) : u;

    int rowE = 2 * i, colE = 2 * j, colEp = 2 * j + 1;
    int rowO = 2 * i + 1;
    int colO = 2 * j + 1;
    int colO2 = (2 * j + 2) & 511;

    float b00 = B[(rowE << 9) + colE ];
    float b01 = B[(rowE << 9) + colEp];
    float b10 = B[(rowO << 9) + colO ];
    float b11 = B[(rowO << 9) + colO2];
    float f1a = F1[(r  << 9) + u];
    float f1b = F1[(r1 << 9) + s1];
    float f2a = F2[(r  << 9) + u];
    float f2b = F2[(r1 << 9) + s1];

    float K0 = 0.5f * (b00 + f1a) + g1 * RSQ2;            // e0a = 0.5*X - K0
    float K1 = b01 - (f2a + g1) * RSQ2;                   // e0b = -X + K1
    float K2 = b10 + f1b - g2;                            // e1a = -X + K2
    float K3 = -2.f * b11 + SQ2F * f2b - g2;              // e1b = 2*X + K3

    const float* Xn = X + ((size_t)(n * CHN) << 18);
    size_t obase = (size_t)(n * CHN) * 65536 + rem;
    int xiE = rowE << 9, xiO = rowO << 9;
#pragma unroll
    for (int c = 0; c < CHN; c++) {
        const float* Xc = Xn + ((size_t)c << 18);
        size_t o = obase + (size_t)c * 65536;
        out[(size_t)SECSZ * 1 + o] = -Xc[xiO + colO ] + K2;        // e1[:, :8]
        out[(size_t)SECSZ * 2 + o] = 0.5f * Xc[xiE + colE] - K0;   // e0[:, :8]
        out[(size_t)SECSZ * 3 + o] = 2.f * Xc[xiO + colO2] + K3;   // e1[:, 8:]
        out[(size_t)SECSZ * 4 + o] = -Xc[xiE + colEp] + K1;        // e0[:, 8:]
    }
}

// ---------------- launch ----------------
extern "C" void kernel_launch(void* const* d_in, const int* in_sizes, int n_in,
                              void* d_out, int out_size) {
    const float* X = (const float*)d_in[0];
    const float* h = (const float*)d_in[1];
    const float* g = (const float*)d_in[2];
    const float* f = (const float*)d_in[3];
    float* out = (float*)d_out;

    ksumrow<<<NBATCH * HH, 128>>>(X, h);
    kpool  <<<2048, 256>>>(h, out);
    kBSd   <<<8192, 256>>>(g);
    kremap1<<<4096, 256>>>();
    kcolq1 <<<4096, 256>>>(f);
    krowq1 <<<4096, 256>>>(f);
    kcolq2 <<<4096, 256>>>(f);
    krowq2 <<<4096, 256>>>(f);
    kremap2<<<2048, 256>>>();
    kcolp1 <<<2048, 256>>>(f);
    krowp1 <<<2048, 256>>>(f);
    kcolp2 <<<2048, 256>>>(f);
    krowp2 <<<2048, 256>>>(f);
    kfinal <<<2048, 256>>>(X, out);
}

// round 5
// speedup vs baseline: 1.1827x; 1.0600x over previous
#include <cuda_runtime.h>
#include <cstdint>

#define NBATCH 8
#define CHN 8
#define HH 512
#define HB 256
#define RSQ2 0.70710678118654752440f
#define SQ2F 1.41421356237309504880f
#define SECSZ (NBATCH*CHN*HB*HB)   /* 4194304 */

// ---------------- scratch ----------------
__device__ float g_Sx [NBATCH*HH*HH];
__device__ float g_T1 [NBATCH*HH*HH];
__device__ float g_B  [NBATCH*HH*HH];
__device__ float g_Sd [NBATCH*HH*HH];
__device__ float g_cp [NBATCH*HB*HB];
__device__ float g_Sp0[NBATCH*HB*HH];
__device__ float g_Sp1[NBATCH*HB*HH];
__device__ float g_Ct [NBATCH*HB*HH];
__device__ float g_F1 [NBATCH*HB*HH];
__device__ float g_Sx0[NBATCH*HB*HH];
__device__ float g_F2 [NBATCH*HB*HH];
__device__ float g_Sxx[NBATCH*HB*HH];
__device__ float g_SP0[NBATCH*HB*HB];
__device__ float g_SP1[NBATCH*HB*HB];
__device__ float g_Dt [NBATCH*HB*HB];
__device__ float g_G1 [NBATCH*HB*HB];
__device__ float g_Se0[NBATCH*HB*HB];
__device__ float g_G2 [NBATCH*HB*HB];

// ---------------- kernels ----------------

// 1) fused: Sx = channel-sum of X  AND  T1 = row conv(h, per) of Sx.
__global__ void ksumrow(const float* __restrict__ X, const float* __restrict__ h) {
    __shared__ float srow[HH];
    int row = blockIdx.x;                       // 0..NBATCH*HH-1
    int n = row >> 9;
    int t = threadIdx.x;                        // 0..127
    const float4* xb = reinterpret_cast<const float4*>(X)
                       + (size_t)n * CHN * 65536 + (size_t)(row & 511) * 128 + t;
    float4 a = xb[0];
#pragma unroll
    for (int c = 1; c < CHN; c++) {
        float4 v = xb[(size_t)c * 65536];
        a.x += v.x; a.y += v.y; a.z += v.z; a.w += v.w;
    }
    reinterpret_cast<float4*>(srow)[t] = a;
    reinterpret_cast<float4*>(g_Sx)[(size_t)row * 128 + t] = a;
    __syncthreads();
    float hv[9];
#pragma unroll
    for (int k = 0; k < 9; k++) hv[k] = h[k];
    float4 o;
    float* op = &o.x;
#pragma unroll
    for (int k = 0; k < 4; k++) {
        int j = 4 * t + k;
        float acc = 0.f;
#pragma unroll
        for (int a2 = 0; a2 < 9; a2++) acc += hv[a2] * srow[(j + a2 - 4) & 511];
        op[k] = acc;
    }
    reinterpret_cast<float4*>(g_T1)[(size_t)row * 128 + t] = o;
}

// 3) col pass of conv h + 2x2 avgpool -> cp ; also write output section 0
__global__ void kpool(const float* __restrict__ h, float* __restrict__ out) {
    int idx = blockIdx.x * blockDim.x + threadIdx.x;      // < NBATCH*HB*HB
    int n = idx >> 16;
    int rem = idx & 65535;
    int p = rem >> 8, q = rem & 255;
    const float* T = g_T1 + ((size_t)n << 18);
    float acc = 0.f;
#pragma unroll
    for (int a = 0; a < 9; a++) {
        int r0 = ((2 * p + a - 4) & 511) << 9;
        int r1 = ((2 * p + 1 + a - 4) & 511) << 9;
        float2 t0 = *reinterpret_cast<const float2*>(T + r0 + 2 * q);
        float2 t1 = *reinterpret_cast<const float2*>(T + r1 + 2 * q);
        acc += h[a] * (t0.x + t0.y + t1.x + t1.y);
    }
    acc *= 0.25f;
    g_cp[idx] = acc;
    size_t base = (size_t)(n * CHN) * 65536 + rem;
#pragma unroll
    for (int c = 0; c < CHN; c++) out[base + (size_t)c * 65536] = acc;
}

// 4) B = 8*conv_per(up2(cp), g x g) polyphase, parity-specialized; Sd = Sx - 8*B
__global__ void kBSd(const float* __restrict__ g) {
    int idx = blockIdx.x * blockDim.x + threadIdx.x;      // < NBATCH*HH*HH
    int n = idx >> 18;
    int i = (idx >> 9) & 511, j = idx & 511;
    const float* cpb = g_cp + ((size_t)n << 16);
    float gv[7];
#pragma unroll
    for (int a = 0; a < 7; a++) gv[a] = g[a];

    float gr[4], gc[4];
    int ir[4], jc[4];
    if (i & 1) {
        gr[0] = gv[0]; gr[1] = gv[2]; gr[2] = gv[4]; gr[3] = gv[6];
        ir[0] = ((i - 3) & 511) >> 1; ir[1] = ((i - 1) & 511) >> 1;
        ir[2] = ((i + 1) & 511) >> 1; ir[3] = ((i + 3) & 511) >> 1;
    } else {
        gr[0] = gv[1]; gr[1] = gv[3]; gr[2] = gv[5]; gr[3] = 0.f;
        ir[0] = ((i - 2) & 511) >> 1; ir[1] = i >> 1;
        ir[2] = ((i + 2) & 511) >> 1; ir[3] = ir[0];
    }
    if (j & 1) {
        gc[0] = gv[0]; gc[1] = gv[2]; gc[2] = gv[4]; gc[3] = gv[6];
        jc[0] = ((j - 3) & 511) >> 1; jc[1] = ((j - 1) & 511) >> 1;
        jc[2] = ((j + 1) & 511) >> 1; jc[3] = ((j + 3) & 511) >> 1;
    } else {
        gc[0] = gv[1]; gc[1] = gv[3]; gc[2] = gv[5]; gc[3] = 0.f;
        jc[0] = ((j - 2) & 511) >> 1; jc[1] = j >> 1;
        jc[2] = ((j + 2) & 511) >> 1; jc[3] = jc[0];
    }
    float acc = 0.f;
#pragma unroll
    for (int a = 0; a < 4; a++) {
        const float* rowp = cpb + (ir[a] << 8);
        float inner = gc[0] * rowp[jc[0]] + gc[1] * rowp[jc[1]]
                    + gc[2] * rowp[jc[2]] + gc[3] * rowp[jc[3]];
        acc += gr[a] * inner;
    }
    float Bs = 8.f * acc;
    g_B[idx] = Bs;
    g_Sd[idx] = g_Sx[idx] - 8.f * Bs;
}

// 5) TILED diagonal remap: Sp0[r,s]=Sd[(r-s)%512,(r+s)%512]; Sp1: col+1.
//    32x32 output tile <- 64x64 coalesced Sd load.
__global__ void kremap1t() {
    __shared__ float tile[64][66];
    int n = blockIdx.z;
    int r0 = blockIdx.y << 5;
    int s0 = blockIdx.x << 5;
    const float* Sd = g_Sd + ((size_t)n << 18);
    int tbase = (r0 - s0 - 31) & 511;
    int vbase = (r0 + s0) & 511;
    int tid = threadIdx.x;                      // 256
#pragma unroll
    for (int it = 0; it < 16; it++) {
        int lr = (it << 2) + (tid >> 6);
        int lc = tid & 63;
        tile[lr][lc] = Sd[(((tbase + lr) & 511) << 9) + ((vbase + lc) & 511)];
    }
    __syncthreads();
    int w = tid >> 5, l = tid & 31;
    int s = s0 + l;
#pragma unroll
    for (int k = 0; k < 4; k++) {
        int dr = w + (k << 3);
        int r = r0 + dr;
        int ti = 31 + dr - l;
        int vi = dr + l;
        size_t o = ((size_t)n << 17) + ((size_t)r << 9) + s;
        g_Sp0[o] = tile[ti][vi];
        g_Sp1[o] = tile[ti][vi + 1];
    }
}

// generic 12-tap periodic column convs
#define DEF_COLF(name, INV, OUTV, W, CL)                                     \
__global__ void name(const float* __restrict__ f) {                          \
    int idx = blockIdx.x * blockDim.x + threadIdx.x;                         \
    int j = idx & (W - 1);                                                   \
    const float* row = INV + (idx - j);                                      \
    float acc = 0.f;                                                         \
    for (int b = 0; b < 12; b++) acc += f[b] * row[(j + b - CL) & (W - 1)];  \
    OUTV[idx] = acc;                                                         \
}
DEF_COLF(kcolq1, g_Sp1, g_Ct, 512, 6)
DEF_COLF(kcolq2, g_Sx0, g_Ct, 512, 5)
DEF_COLF(kcolp1, g_SP1, g_Dt, 256, 6)
DEF_COLF(kcolp2, g_Se0, g_Dt, 256, 5)

// 7) qper_col row pass (ru=6) -> F1 ; Sx0 = (Sp0 - 8F1)/sqrt2
__global__ void krowq1(const float* __restrict__ f) {
    int idx = blockIdx.x * blockDim.x + threadIdx.x;      // < NBATCH*HB*HH
    int rem = idx & 131071;
    int r = rem >> 9, s = idx & 511;
    const float* C = g_Ct + (idx - rem);
    float acc = 0.f;
#pragma unroll
    for (int a = 0; a < 12; a++) {
        int t = r + a - 6;
        float v = ((unsigned)t < 256u) ? C[(t << 9) + s]
                                       : C[((t & 255) << 9) + ((s + 256) & 511)];
        acc += f[a] * v;
    }
    g_F1[idx] = acc;
    g_Sx0[idx] = (g_Sp0[idx] - 8.f * acc) * RSQ2;
}

// 9) qper_col row pass (ru=5) -> F2 ; Sxx = Sx0 - sqrt2*Sp1 - 8*F2
__global__ void krowq2(const float* __restrict__ f) {
    int idx = blockIdx.x * blockDim.x + threadIdx.x;
    int rem = idx & 131071;
    int r = rem >> 9, s = idx & 511;
    const float* C = g_Ct + (idx - rem);
    float acc = 0.f;
#pragma unroll
    for (int a = 0; a < 12; a++) {
        int t = r + a - 5;
        float v = ((unsigned)t < 256u) ? C[(t << 9) + s]
                                       : C[((t & 255) << 9) + ((s + 256) & 511)];
        acc += f[a] * v;
    }
    g_F2[idx] = acc;
    g_Sxx[idx] = g_Sx0[idx] - SQ2F * g_Sp1[idx] - 8.f * acc;
}

// 10) TILED level-2 quincunx remap.
//     Fast path (d0 constant in tile, no ipj==255): 64x64 smem tile of Sxx.
//     Slow path only for tiles with i0+j0==224 (straddle band).
__global__ void kremap2t() {
    int n = blockIdx.z;
    int i0 = blockIdx.y << 5;
    int j0 = blockIdx.x << 5;
    const float* Sxx = g_Sxx + ((size_t)n << 17);
    int tid = threadIdx.x;
    int w = tid >> 5, l = tid & 31;
    int S = i0 + j0;
    if (S == 224) {
#pragma unroll
        for (int k = 0; k < 4; k++) {
            int i = i0 + w + (k << 3), j = j0 + l;
            int ipj = i + j;
            int u = (j - i + ((ipj >= 256) ? 256 : 0)) & 511;
            int I1 = (ipj + 1) & 255;
            int s1 = (ipj == 255) ? (2 * j + 1) : u;
            size_t o = ((size_t)n << 16) + ((size_t)i << 8) + j;
            g_SP0[o] = Sxx[((ipj & 255) << 9) + u];
            g_SP1[o] = Sxx[(I1 << 9) + s1];
        }
        return;
    }
    __shared__ float tile[64][66];
    int d0 = (S >= 256) ? 256 : 0;
    int Ibase = S & 255;                        // Ibase+63 <= 255 guaranteed
    int ubase = (j0 - i0 - 31 + d0) & 511;
#pragma unroll
    for (int it = 0; it < 16; it++) {
        int lr = (it << 2) + (tid >> 6);
        int lc = tid & 63;
        tile[lr][lc] = Sxx[((Ibase + lr) << 9) + ((ubase + lc) & 511)];
    }
    __syncthreads();
    int j = j0 + l;
#pragma unroll
    for (int k = 0; k < 4; k++) {
        int di = w + (k << 3);
        int i = i0 + di;
        int lr = di + l;
        int lc = l - di + 31;
        size_t o = ((size_t)n << 16) + ((size_t)i << 8) + j;
        g_SP0[o] = tile[lr][lc];
        g_SP1[o] = tile[lr + 1][lc];
    }
}

// 12) per row pass (ru=6) -> G1 ; Se0 = (SP0 - 16 G1)/sqrt2
__global__ void krowp1(const float* __restrict__ f) {
    int idx = blockIdx.x * blockDim.x + threadIdx.x;      // < NBATCH*HB*HB
    int rem = idx & 65535;
    int i = rem >> 8, j = idx & 255;
    const float* D = g_Dt + (idx - rem);
    float acc = 0.f;
#pragma unroll
    for (int a = 0; a < 12; a++)
        acc += f[a] * D[(((i + a - 6) & 255) << 8) + j];
    g_G1[idx] = acc;
    g_Se0[idx] = (g_SP0[idx] - 16.f * acc) * RSQ2;
}

// 14) per row pass (ru=5) -> G2
__global__ void krowp2(const float* __restrict__ f) {
    int idx = blockIdx.x * blockDim.x + threadIdx.x;
    int rem = idx & 65535;
    int i = rem >> 8, j = idx & 255;
    const float* D = g_Dt + (idx - rem);
    float acc = 0.f;
#pragma unroll
    for (int a = 0; a < 12; a++)
        acc += f[a] * D[(((i + a - 5) & 255) << 8) + j];
    g_G2[idx] = acc;
}

// 15) final combine.
__global__ void kfinal(const float* __restrict__ X, float* __restrict__ out) {
    int idx = blockIdx.x * blockDim.x + threadIdx.x;      // < NBATCH*HB*HB
    int n = idx >> 16;
    int rem = idx & 65535;
    int i = rem >> 8, j = rem & 255;

    const float* B  = g_B  + ((size_t)n << 18);
    const float* F1 = g_F1 + ((size_t)n << 17);
    const float* F2 = g_F2 + ((size_t)n << 17);
    float g1 = g_G1[idx], g2 = g_G2[idx];

    int ipj = i + j;
    int d0 = (ipj >= 256) ? 256 : 0;
    int u  = (j - i + d0) & 511;
    int r  = ipj & 255;
    int r1 = (ipj + 1) & 255;
    int s1 = (ipj == 255) ? (2 * j + 1) : u;

    int rowE = 2 * i, colE = 2 * j, colEp = 2 * j + 1;
    int rowO = 2 * i + 1;
    int colO = 2 * j + 1;
    int colO2 = (2 * j + 2) & 511;

    float b00 = B[(rowE << 9) + colE ];
    float b01 = B[(rowE << 9) + colEp];
    float b10 = B[(rowO << 9) + colO ];
    float b11 = B[(rowO << 9) + colO2];
    float f1a = F1[(r  << 9) + u];
    float f1b = F1[(r1 << 9) + s1];
    float f2a = F2[(r  << 9) + u];
    float f2b = F2[(r1 << 9) + s1];

    float K0 = 0.5f * (b00 + f1a) + g1 * RSQ2;            // e0a = 0.5*X - K0
    float K1 = b01 - (f2a + g1) * RSQ2;                   // e0b = -X + K1
    float K2 = b10 + f1b - g2;                            // e1a = -X + K2
    float K3 = -2.f * b11 + SQ2F * f2b - g2;              // e1b = 2*X + K3

    const float* Xn = X + ((size_t)(n * CHN) << 18);
    size_t obase = (size_t)(n * CHN) * 65536 + rem;
    int xiE = rowE << 9, xiO = rowO << 9;
#pragma unroll
    for (int c = 0; c < CHN; c++) {
        const float* Xc = Xn + ((size_t)c << 18);
        size_t o = obase + (size_t)c * 65536;
        out[(size_t)SECSZ * 1 + o] = -Xc[xiO + colO ] + K2;        // e1[:, :8]
        out[(size_t)SECSZ * 2 + o] = 0.5f * Xc[xiE + colE] - K0;   // e0[:, :8]
        out[(size_t)SECSZ * 3 + o] = 2.f * Xc[xiO + colO2] + K3;   // e1[:, 8:]
        out[(size_t)SECSZ * 4 + o] = -Xc[xiE + colEp] + K1;        // e0[:, 8:]
    }
}

// ---------------- launch ----------------
extern "C" void kernel_launch(void* const* d_in, const int* in_sizes, int n_in,
                              void* d_out, int out_size) {
    const float* X = (const float*)d_in[0];
    const float* h = (const float*)d_in[1];
    const float* g = (const float*)d_in[2];
    const float* f = (const float*)d_in[3];
    float* out = (float*)d_out;

    ksumrow <<<NBATCH * HH, 128>>>(X, h);
    kpool   <<<2048, 256>>>(h, out);
    kBSd    <<<8192, 256>>>(g);
    kremap1t<<<dim3(16, 8, NBATCH), 256>>>();
    kcolq1  <<<4096, 256>>>(f);
    krowq1  <<<4096, 256>>>(f);
    kcolq2  <<<4096, 256>>>(f);
    krowq2  <<<4096, 256>>>(f);
    kremap2t<<<dim3(8, 8, NBATCH), 256>>>();
    kcolp1  <<<2048, 256>>>(f);
    krowp1  <<<2048, 256>>>(f);
    kcolp2  <<<2048, 256>>>(f);
    krowp2  <<<2048, 256>>>(f);
    kfinal  <<<2048, 256>>>(X, out);
}

// round 6
// speedup vs baseline: 1.3345x; 1.1283x over previous
#include <cuda_runtime.h>
#include <cstdint>

#define NBATCH 8
#define CHN 8
#define HH 512
#define HB 256
#define RSQ2 0.70710678118654752440f
#define SQ2F 1.41421356237309504880f
#define SECSZ (NBATCH*CHN*HB*HB)   /* 4194304 */

// ---------------- scratch ----------------
__device__ float g_Sx [NBATCH*HH*HH];
__device__ float g_T1 [NBATCH*HH*HH];
__device__ float g_B  [NBATCH*HH*HH];
__device__ float g_Sd [NBATCH*HH*HH];
__device__ float g_cp [NBATCH*HB*HB];
__device__ float g_Sp0[NBATCH*HB*HH];
__device__ float g_Sp1[NBATCH*HB*HH];
__device__ float g_F1 [NBATCH*HB*HH];
__device__ float g_Sx0[NBATCH*HB*HH];
__device__ float g_F2 [NBATCH*HB*HH];
__device__ float g_Sxx[NBATCH*HB*HH];
__device__ float g_SP0[NBATCH*HB*HB];
__device__ float g_SP1[NBATCH*HB*HB];
__device__ float g_G1 [NBATCH*HB*HB];
__device__ float g_Se0[NBATCH*HB*HB];
__device__ float g_G2 [NBATCH*HB*HB];

// ---------------- kernels ----------------

// 1) fused: Sx = channel-sum of X  AND  T1 = row conv(h, per) of Sx.
__global__ void ksumrow(const float* __restrict__ X, const float* __restrict__ h) {
    __shared__ float srow[HH];
    int row = blockIdx.x;                       // 0..NBATCH*HH-1
    int n = row >> 9;
    int t = threadIdx.x;                        // 0..127
    const float4* xb = reinterpret_cast<const float4*>(X)
                       + (size_t)n * CHN * 65536 + (size_t)(row & 511) * 128 + t;
    float4 a = xb[0];
#pragma unroll
    for (int c = 1; c < CHN; c++) {
        float4 v = xb[(size_t)c * 65536];
        a.x += v.x; a.y += v.y; a.z += v.z; a.w += v.w;
    }
    reinterpret_cast<float4*>(srow)[t] = a;
    reinterpret_cast<float4*>(g_Sx)[(size_t)row * 128 + t] = a;
    __syncthreads();
    float hv[9];
#pragma unroll
    for (int k = 0; k < 9; k++) hv[k] = h[k];
    float4 o;
    float* op = &o.x;
#pragma unroll
    for (int k = 0; k < 4; k++) {
        int j = 4 * t + k;
        float acc = 0.f;
#pragma unroll
        for (int a2 = 0; a2 < 9; a2++) acc += hv[a2] * srow[(j + a2 - 4) & 511];
        op[k] = acc;
    }
    reinterpret_cast<float4*>(g_T1)[(size_t)row * 128 + t] = o;
}

// 3) col pass of conv h + 2x2 avgpool -> cp ; also write output section 0
__global__ void kpool(const float* __restrict__ h, float* __restrict__ out) {
    int idx = blockIdx.x * blockDim.x + threadIdx.x;      // < NBATCH*HB*HB
    int n = idx >> 16;
    int rem = idx & 65535;
    int p = rem >> 8, q = rem & 255;
    const float* T = g_T1 + ((size_t)n << 18);
    float acc = 0.f;
#pragma unroll
    for (int a = 0; a < 9; a++) {
        int r0 = ((2 * p + a - 4) & 511) << 9;
        int r1 = ((2 * p + 1 + a - 4) & 511) << 9;
        float2 t0 = *reinterpret_cast<const float2*>(T + r0 + 2 * q);
        float2 t1 = *reinterpret_cast<const float2*>(T + r1 + 2 * q);
        acc += h[a] * (t0.x + t0.y + t1.x + t1.y);
    }
    acc *= 0.25f;
    g_cp[idx] = acc;
    size_t base = (size_t)(n * CHN) * 65536 + rem;
#pragma unroll
    for (int c = 0; c < CHN; c++) out[base + (size_t)c * 65536] = acc;
}

// 4) B = 8*conv_per(up2(cp), g x g) polyphase, parity-specialized; Sd = Sx - 8*B
__global__ void kBSd(const float* __restrict__ g) {
    int idx = blockIdx.x * blockDim.x + threadIdx.x;      // < NBATCH*HH*HH
    int n = idx >> 18;
    int i = (idx >> 9) & 511, j = idx & 511;
    const float* cpb = g_cp + ((size_t)n << 16);
    float gv[7];
#pragma unroll
    for (int a = 0; a < 7; a++) gv[a] = g[a];

    float gr[4], gc[4];
    int ir[4], jc[4];
    if (i & 1) {
        gr[0] = gv[0]; gr[1] = gv[2]; gr[2] = gv[4]; gr[3] = gv[6];
        ir[0] = ((i - 3) & 511) >> 1; ir[1] = ((i - 1) & 511) >> 1;
        ir[2] = ((i + 1) & 511) >> 1; ir[3] = ((i + 3) & 511) >> 1;
    } else {
        gr[0] = gv[1]; gr[1] = gv[3]; gr[2] = gv[5]; gr[3] = 0.f;
        ir[0] = ((i - 2) & 511) >> 1; ir[1] = i >> 1;
        ir[2] = ((i + 2) & 511) >> 1; ir[3] = ir[0];
    }
    if (j & 1) {
        gc[0] = gv[0]; gc[1] = gv[2]; gc[2] = gv[4]; gc[3] = gv[6];
        jc[0] = ((j - 3) & 511) >> 1; jc[1] = ((j - 1) & 511) >> 1;
        jc[2] = ((j + 1) & 511) >> 1; jc[3] = ((j + 3) & 511) >> 1;
    } else {
        gc[0] = gv[1]; gc[1] = gv[3]; gc[2] = gv[5]; gc[3] = 0.f;
        jc[0] = ((j - 2) & 511) >> 1; jc[1] = j >> 1;
        jc[2] = ((j + 2) & 511) >> 1; jc[3] = jc[0];
    }
    float acc = 0.f;
#pragma unroll
    for (int a = 0; a < 4; a++) {
        const float* rowp = cpb + (ir[a] << 8);
        float inner = gc[0] * rowp[jc[0]] + gc[1] * rowp[jc[1]]
                    + gc[2] * rowp[jc[2]] + gc[3] * rowp[jc[3]];
        acc += gr[a] * inner;
    }
    float Bs = 8.f * acc;
    g_B[idx] = Bs;
    g_Sd[idx] = g_Sx[idx] - 8.f * Bs;
}

// 5) TILED diagonal remap: Sp0[r,s]=Sd[(r-s)%512,(r+s)%512]; Sp1: col+1.
__global__ void kremap1t() {
    __shared__ float tile[64][66];
    int n = blockIdx.z;
    int r0 = blockIdx.y << 5;
    int s0 = blockIdx.x << 5;
    const float* Sd = g_Sd + ((size_t)n << 18);
    int tbase = (r0 - s0 - 31) & 511;
    int vbase = (r0 + s0) & 511;
    int tid = threadIdx.x;                      // 256
#pragma unroll
    for (int it = 0; it < 16; it++) {
        int lr = (it << 2) + (tid >> 6);
        int lc = tid & 63;
        tile[lr][lc] = Sd[(((tbase + lr) & 511) << 9) + ((vbase + lc) & 511)];
    }
    __syncthreads();
    int w = tid >> 5, l = tid & 31;
    int s = s0 + l;
#pragma unroll
    for (int k = 0; k < 4; k++) {
        int dr = w + (k << 3);
        int r = r0 + dr;
        int ti = 31 + dr - l;
        int vi = dr + l;
        size_t o = ((size_t)n << 17) + ((size_t)r << 9) + s;
        g_Sp0[o] = tile[ti][vi];
        g_Sp1[o] = tile[ti][vi + 1];
    }
}

// ---- fused separable 12-tap conv (col pass then row pass) on a 256xW field ----
// QPER: rows extend with column shift W/2 (qper_col); else plain periodic.
// CL: conv center (6 for shift(1,1), 5 for shift(0,0)).
template<int W, bool QPER, int CL>
__device__ __forceinline__ void conv_ff(const float* __restrict__ inb,
                                        const float* __restrict__ f,
                                        int r0, int s0, int tid, float (&F)[4]) {
    __shared__ float ti[44][45];
    __shared__ float tc[44][33];
    float fv[12];
#pragma unroll
    for (int k = 0; k < 12; k++) fv[k] = f[k];
    constexpr int LSH = (W == 512) ? 9 : 8;
    for (int e = tid; e < 44 * 44; e += 256) {
        int lt = e / 44, ls = e - lt * 44;
        int t = r0 + lt - 6;
        int s = s0 + ls - 6;
        int sr, sc;
        if (QPER) {
            if ((unsigned)t < 256u) { sr = t; sc = s & (W - 1); }
            else { sr = t & 255; sc = (s + (W / 2)) & (W - 1); }
        } else { sr = t & 255; sc = s & (W - 1); }
        ti[lt][ls] = inb[(sr << LSH) + sc];
    }
    __syncthreads();
    for (int e = tid; e < 44 * 32; e += 256) {
        int lt = e >> 5, lo = e & 31;
        float acc = 0.f;
#pragma unroll
        for (int b = 0; b < 12; b++) acc += fv[b] * ti[lt][lo + b + (6 - CL)];
        tc[lt][lo] = acc;
    }
    __syncthreads();
    int w = tid >> 5, l = tid & 31;
#pragma unroll
    for (int k = 0; k < 4; k++) {
        int li = w + (k << 3);
        float acc = 0.f;
#pragma unroll
        for (int a = 0; a < 12; a++) acc += fv[a] * tc[li + a + (6 - CL)][l];
        F[k] = acc;
    }
}

// 6+7) F1 = conv_qper(Sp1) ; Sx0 = (Sp0 - 8*F1)/sqrt2
__global__ void kconvq1(const float* __restrict__ f) {
    int n = blockIdx.z, r0 = blockIdx.y << 5, s0 = blockIdx.x << 5;
    int tid = threadIdx.x;
    float F[4];
    conv_ff<512, true, 6>(g_Sp1 + ((size_t)n << 17), f, r0, s0, tid, F);
    int w = tid >> 5, l = tid & 31;
    size_t base = ((size_t)n << 17) + s0 + l;
#pragma unroll
    for (int k = 0; k < 4; k++) {
        size_t o = base + ((size_t)(r0 + w + (k << 3)) << 9);
        g_F1[o] = F[k];
        g_Sx0[o] = (g_Sp0[o] - 8.f * F[k]) * RSQ2;
    }
}

// 8+9) F2 = conv_qper(Sx0, shift0) ; Sxx = Sx0 - sqrt2*Sp1 - 8*F2
__global__ void kconvq2(const float* __restrict__ f) {
    int n = blockIdx.z, r0 = blockIdx.y << 5, s0 = blockIdx.x << 5;
    int tid = threadIdx.x;
    float F[4];
    conv_ff<512, true, 5>(g_Sx0 + ((size_t)n << 17), f, r0, s0, tid, F);
    int w = tid >> 5, l = tid & 31;
    size_t base = ((size_t)n << 17) + s0 + l;
#pragma unroll
    for (int k = 0; k < 4; k++) {
        size_t o = base + ((size_t)(r0 + w + (k << 3)) << 9);
        g_F2[o] = F[k];
        g_Sxx[o] = g_Sx0[o] - SQ2F * g_Sp1[o] - 8.f * F[k];
    }
}

// 10) TILED level-2 quincunx remap.
__global__ void kremap2t() {
    int n = blockIdx.z;
    int i0 = blockIdx.y << 5;
    int j0 = blockIdx.x << 5;
    const float* Sxx = g_Sxx + ((size_t)n << 17);
    int tid = threadIdx.x;
    int w = tid >> 5, l = tid & 31;
    int S = i0 + j0;
    if (S == 224) {
#pragma unroll
        for (int k = 0; k < 4; k++) {
            int i = i0 + w + (k << 3), j = j0 + l;
            int ipj = i + j;
            int u = (j - i + ((ipj >= 256) ? 256 : 0)) & 511;
            int I1 = (ipj + 1) & 255;
            int s1 = (ipj == 255) ? (2 * j + 1) : u;
            size_t o = ((size_t)n << 16) + ((size_t)i << 8) + j;
            g_SP0[o] = Sxx[((ipj & 255) << 9) + u];
            g_SP1[o] = Sxx[(I1 << 9) + s1];
        }
        return;
    }
    __shared__ float tile[64][66];
    int d0 = (S >= 256) ? 256 : 0;
    int Ibase = S & 255;
    int ubase = (j0 - i0 - 31 + d0) & 511;
#pragma unroll
    for (int it = 0; it < 16; it++) {
        int lr = (it << 2) + (tid >> 6);
        int lc = tid & 63;
        tile[lr][lc] = Sxx[((Ibase + lr) << 9) + ((ubase + lc) & 511)];
    }
    __syncthreads();
    int j = j0 + l;
#pragma unroll
    for (int k = 0; k < 4; k++) {
        int di = w + (k << 3);
        int i = i0 + di;
        int lr = di + l;
        int lc = l - di + 31;
        size_t o = ((size_t)n << 16) + ((size_t)i << 8) + j;
        g_SP0[o] = tile[lr][lc];
        g_SP1[o] = tile[lr + 1][lc];
    }
}

// 11+12) G1 = conv_per(SP1) ; Se0 = (SP0 - 16*G1)/sqrt2
__global__ void kconvp1(const float* __restrict__ f) {
    int n = blockIdx.z, r0 = blockIdx.y << 5, s0 = blockIdx.x << 5;
    int tid = threadIdx.x;
    float F[4];
    conv_ff<256, false, 6>(g_SP1 + ((size_t)n << 16), f, r0, s0, tid, F);
    int w = tid >> 5, l = tid & 31;
    size_t base = ((size_t)n << 16) + s0 + l;
#pragma unroll
    for (int k = 0; k < 4; k++) {
        size_t o = base + ((size_t)(r0 + w + (k << 3)) << 8);
        g_G1[o] = F[k];
        g_Se0[o] = (g_SP0[o] - 16.f * F[k]) * RSQ2;
    }
}

// 13+14) G2 = conv_per(Se0, shift0)
__global__ void kconvp2(const float* __restrict__ f) {
    int n = blockIdx.z, r0 = blockIdx.y << 5, s0 = blockIdx.x << 5;
    int tid = threadIdx.x;
    float F[4];
    conv_ff<256, false, 5>(g_Se0 + ((size_t)n << 16), f, r0, s0, tid, F);
    int w = tid >> 5, l = tid & 31;
    size_t base = ((size_t)n << 16) + s0 + l;
#pragma unroll
    for (int k = 0; k < 4; k++) {
        size_t o = base + ((size_t)(r0 + w + (k << 3)) << 8);
        g_G2[o] = F[k];
    }
}

// 15) final combine.
__global__ void kfinal(const float* __restrict__ X, float* __restrict__ out) {
    int idx = blockIdx.x * blockDim.x + threadIdx.x;      // < NBATCH*HB*HB
    int n = idx >> 16;
    int rem = idx & 65535;
    int i = rem >> 8, j = rem & 255;

    const float* B  = g_B  + ((size_t)n << 18);
    const float* F1 = g_F1 + ((size_t)n << 17);
    const float* F2 = g_F2 + ((size_t)n << 17);
    float g1 = g_G1[idx], g2 = g_G2[idx];

    int ipj = i + j;
    int d0 = (ipj >= 256) ? 256 : 0;
    int u  = (j - i + d0) & 511;
    int r  = ipj & 255;
    int r1 = (ipj + 1) & 255;
    int s1 = (ipj == 255) ? (2 * j + 1) : u;

    int rowE = 2 * i, colE = 2 * j, colEp = 2 * j + 1;
    int rowO = 2 * i + 1;
    int colO = 2 * j + 1;
    int colO2 = (2 * j + 2) & 511;

    float b00 = B[(rowE << 9) + colE ];
    float b01 = B[(rowE << 9) + colEp];
    float b10 = B[(rowO << 9) + colO ];
    float b11 = B[(rowO << 9) + colO2];
    float f1a = F1[(r  << 9) + u];
    float f1b = F1[(r1 << 9) + s1];
    float f2a = F2[(r  << 9) + u];
    float f2b = F2[(r1 << 9) + s1];

    float K0 = 0.5f * (b00 + f1a) + g1 * RSQ2;            // e0a = 0.5*X - K0
    float K1 = b01 - (f2a + g1) * RSQ2;                   // e0b = -X + K1
    float K2 = b10 + f1b - g2;                            // e1a = -X + K2
    float K3 = -2.f * b11 + SQ2F * f2b - g2;              // e1b = 2*X + K3

    const float* Xn = X + ((size_t)(n * CHN) << 18);
    size_t obase = (size_t)(n * CHN) * 65536 + rem;
    int xiE = rowE << 9, xiO = rowO << 9;
#pragma unroll
    for (int c = 0; c < CHN; c++) {
        const float* Xc = Xn + ((size_t)c << 18);
        size_t o = obase + (size_t)c * 65536;
        out[(size_t)SECSZ * 1 + o] = -Xc[xiO + colO ] + K2;        // e1[:, :8]
        out[(size_t)SECSZ * 2 + o] = 0.5f * Xc[xiE + colE] - K0;   // e0[:, :8]
        out[(size_t)SECSZ * 3 + o] = 2.f * Xc[xiO + colO2] + K3;   // e1[:, 8:]
        out[(size_t)SECSZ * 4 + o] = -Xc[xiE + colEp] + K1;        // e0[:, 8:]
    }
}

// ---------------- launch ----------------
extern "C" void kernel_launch(void* const* d_in, const int* in_sizes, int n_in,
                              void* d_out, int out_size) {
    const float* X = (const float*)d_in[0];
    const float* h = (const float*)d_in[1];
    const float* g = (const float*)d_in[2];
    const float* f = (const float*)d_in[3];
    float* out = (float*)d_out;

    ksumrow <<<NBATCH * HH, 128>>>(X, h);
    kpool   <<<2048, 256>>>(h, out);
    kBSd    <<<8192, 256>>>(g);
    kremap1t<<<dim3(16, 8, NBATCH), 256>>>();
    kconvq1 <<<dim3(16, 8, NBATCH), 256>>>(f);
    kconvq2 <<<dim3(16, 8, NBATCH), 256>>>(f);
    kremap2t<<<dim3(8, 8, NBATCH), 256>>>();
    kconvp1 <<<dim3(8, 8, NBATCH), 256>>>(f);
    kconvp2 <<<dim3(8, 8, NBATCH), 256>>>(f);
    kfinal  <<<2048, 256>>>(X, out);
}